// round 14
// baseline (speedup 1.0000x reference)
#include <cuda_runtime.h>
#include <math.h>
#include <float.h>

#define Bc 2
#define Mc 8192
#define Nc (Bc * Mc)
#define KF 16
#define KN 8
#define NB 4096
#define BCAP 64
#define NCELL 32768             // 32^3 morton cells

#define QPB 64                  // queries per block (knn/select)
#define SPLITS 8
#define KTH 512
#define QBLKS 128               // per cloud; knn grid = 256
#define PASS_CANDS 4096         // candidates staged per pass (64KB SoA)
#define SCAP 64                 // survivor cap per (query, slice)
#define CCAP 2048               // compacted-candidate cap per window
#define CPAD (CCAP + 32)

// ---- scratch (device globals; no allocation allowed) ----
__device__ int      g_knn[(size_t)Nc * KF];
__device__ double   g_acc[8];
__device__ int      g_hist[Bc][NB];
__device__ int      g_pref[Bc][NB];
__device__ int      g_members[Bc][NB * BCAP];
__device__ int      g_nflag;
__device__ int      g_flagq[Nc];
__device__ unsigned g_survk[Nc][SPLITS][SCAP];  // (d18)<<13 | idx13
__device__ int      g_cnt[Nc][SPLITS];
__device__ int      g_chist[Bc][NCELL];
__device__ int      g_cpref[Bc][NCELL];
__device__ int      g_cfill[Bc][NCELL];
__device__ int      g_qperm[Bc * Mc];

// ----- u32 compare-exchange: a=min, b=max -----
__device__ __forceinline__ void cx(unsigned& a, unsigned& b) {
    unsigned lo = min(a, b);
    b = max(a, b);
    a = lo;
}

__device__ __forceinline__ void sort8(unsigned k[8]) {
    cx(k[0],k[1]); cx(k[2],k[3]); cx(k[4],k[5]); cx(k[6],k[7]);
    cx(k[0],k[2]); cx(k[1],k[3]); cx(k[4],k[6]); cx(k[5],k[7]);
    cx(k[1],k[2]); cx(k[5],k[6]);
    cx(k[0],k[4]); cx(k[1],k[5]); cx(k[2],k[6]); cx(k[3],k[7]);
    cx(k[2],k[4]); cx(k[3],k[5]);
    cx(k[1],k[2]); cx(k[3],k[4]); cx(k[5],k[6]);
}

__device__ __forceinline__ void clean8(unsigned k[8]) {
    cx(k[0],k[4]); cx(k[1],k[5]); cx(k[2],k[6]); cx(k[3],k[7]);
    cx(k[0],k[2]); cx(k[1],k[3]); cx(k[4],k[6]); cx(k[5],k[7]);
    cx(k[0],k[1]); cx(k[2],k[3]); cx(k[4],k[5]); cx(k[6],k[7]);
}

__device__ __forceinline__ void clean16(unsigned k[16]) {
#pragma unroll
    for (int j = 8; j; j >>= 1)
#pragma unroll
        for (int i = 0; i < 16; ++i) {
            int l = i ^ j;
            if (l > i) cx(k[i], k[l]);
        }
}

#define MRGU(SRC_A, SRC_B, LEN, DSTSTMT)                                      \
    {                                                                         \
        int ii = 0, jj = 0;                                                   \
        _Pragma("unroll 1")                                                   \
        for (int r = 0; r < 16; ++r) {                                        \
            unsigned a = (SRC_A)[min(ii, (LEN) - 1)];                         \
            unsigned b = (SRC_B)[min(jj, (LEN) - 1)];                         \
            bool takeA = (jj >= (LEN)) || ((ii < (LEN)) && (a <= b));         \
            unsigned o = takeA ? a : b;                                       \
            ii += takeA; jj += !takeA;                                        \
            DSTSTMT;                                                          \
        }                                                                     \
    }

// 4 distances from SoA via float4 loads: d = ax*x + ay*y + az*z + (w + qw)
__device__ __forceinline__ void dist4s(const float* __restrict__ xs,
                                       const float* __restrict__ ys,
                                       const float* __restrict__ zs,
                                       const float* __restrict__ ws, int j0,
                                       float ax, float ay, float az, float qw,
                                       float d[4]) {
    float4 X = *(const float4*)(xs + j0);
    float4 Y = *(const float4*)(ys + j0);
    float4 Z = *(const float4*)(zs + j0);
    float4 W = *(const float4*)(ws + j0);
    d[0] = fmaf(ax, X.x, fmaf(ay, Y.x, fmaf(az, Z.x, W.x + qw)));
    d[1] = fmaf(ax, X.y, fmaf(ay, Y.y, fmaf(az, Z.y, W.y + qw)));
    d[2] = fmaf(ax, X.z, fmaf(ay, Y.z, fmaf(az, Z.z, W.z + qw)));
    d[3] = fmaf(ax, X.w, fmaf(ay, Y.w, fmaf(az, Z.w, W.w + qw)));
}

// Morton bit expansion (10-bit safe; used with 5 bits)
__device__ __forceinline__ unsigned expand3(unsigned v) {
    v &= 0x3FFu;
    v = (v | (v << 16)) & 0x030000FFu;
    v = (v | (v << 8))  & 0x0300F00Fu;
    v = (v | (v << 4))  & 0x030C30C3u;
    v = (v | (v << 2))  & 0x09249249u;
    return v;
}
__device__ __forceinline__ unsigned morton_of(float x, float y, float z) {
    int mx = min(31, max(0, (int)((x + 8.0f) * 2.0f)));
    int my = min(31, max(0, (int)((y + 8.0f) * 2.0f)));
    int mz = min(31, max(0, (int)((z + 8.0f) * 2.0f)));
    return expand3((unsigned)mx) | (expand3((unsigned)my) << 1)
         | (expand3((unsigned)mz) << 2);
}

// ---- knn smem layout (byte offsets) ----
#define SM_STAGE   0                         // 4 arrays x 4096 x 4 = 65536
#define SM_COMPACT 65536                     // 5 arrays x CPAD x 4 = 41600
#define SM_TAU     (SM_COMPACT + CPAD * 5 * 4)   // 107136; 64 x u32
#define SM_SX      (SM_TAU + 256)
#define SM_SY      (SM_SX + 256)
#define SM_SZ      (SM_SY + 256)
#define SM_ST      (SM_SZ + 256)
#define SM_STATF   (SM_ST + 256)             // 4 floats
#define SM_KC      (SM_STATF + 16)           // 1 int
#define SM_WSUM    (SM_KC + 16)              // 16 ints
#define SM_KNN_TOTAL (SM_WSUM + 64)          // 108512

// ================= Kernel A: tau + block-pruned filter =================
extern "C" __global__ void __launch_bounds__(KTH, 2)
knn_kernel(const float* __restrict__ coords) {
    extern __shared__ unsigned char sraw[];
    float* xs = (float*)(sraw + SM_STAGE);
    float* ys = xs + PASS_CANDS;
    float* zs = ys + PASS_CANDS;
    float* ws = zs + PASS_CANDS;
    float* ccx = (float*)(sraw + SM_COMPACT);
    float* ccy = ccx + CPAD;
    float* ccz = ccy + CPAD;
    float* ccw = ccz + CPAD;
    int*   cidx = (int*)(ccw + CPAD);
    unsigned* bufA = (unsigned*)(sraw + SM_COMPACT);   // overlay (pre-Phase-B)
    unsigned* bufB = bufA + QPB * 68;
    unsigned* tau_sm = (unsigned*)(sraw + SM_TAU);
    float* sx = (float*)(sraw + SM_SX);
    float* sy = (float*)(sraw + SM_SY);
    float* sz = (float*)(sraw + SM_SZ);
    float* st = (float*)(sraw + SM_ST);
    float* statf = (float*)(sraw + SM_STATF);
    int*   kcS = (int*)(sraw + SM_KC);
    int*   wsS = (int*)(sraw + SM_WSUM);

    const int tid = threadIdx.x;
    const int cloud = blockIdx.x >> 7;
    const int qblk = blockIdx.x & 127;
    const int qLocal = tid & (QPB - 1);
    const int split = tid >> 6;            // warp-uniform

    const float* cb = coords + (size_t)cloud * Mc * 3;
    const float4* cp = (const float4*)cb;
    const int q = g_qperm[cloud * Mc + qblk * QPB + qLocal];
    const int gq = cloud * Mc + q;

    const float qx = cb[3 * q], qy = cb[3 * q + 1], qz = cb[3 * q + 2];
    const float qw = fmaf(qx, qx, fmaf(qy, qy, qz * qz));
    const float ax = -2.0f * qx, ay = -2.0f * qy, az = -2.0f * qz;
    const int sbase = split << 9;

    // ---------- Phase A: keep-8 over 512-point sample, direct uniform LDG ----------
    unsigned tk[8];
#pragma unroll
    for (int t = 0; t < 8; ++t) tk[t] = 0xFFFFFFFFu;

#pragma unroll 1
    for (int b = 0; b < 8; ++b) {
        const int j0 = (b < 4) ? (sbase + b * 8)
                               : (PASS_CANDS + sbase + (b - 4) * 8);
        const float4* p = cp + ((3 * j0) >> 2);   // j0 % 8 == 0 -> aligned
        float4 A = p[0], Bv = p[1], C = p[2], D = p[3], E = p[4], F = p[5];
        float x8[8] = {A.x, A.w, Bv.z, C.y, D.x, D.w, E.z, F.y};
        float y8[8] = {A.y, Bv.x, Bv.w, C.z, D.y, E.x, E.w, F.z};
        float z8[8] = {A.z, Bv.y, C.x, C.w, D.z, E.y, F.x, F.w};
        unsigned bk[8];
#pragma unroll
        for (int i = 0; i < 8; ++i) {
            float w = fmaf(x8[i], x8[i], fmaf(y8[i], y8[i], z8[i] * z8[i]));
            float d = fmaf(ax, x8[i], fmaf(ay, y8[i], fmaf(az, z8[i], w + qw)));
            bk[i] = __float_as_uint(d) & 0x7FFFF800u;
        }
        sort8(bk);
#pragma unroll
        for (int i = 0; i < 8; ++i) tk[i] = min(tk[i], bk[7 - i]);
        clean8(tk);
    }

    // ---------- merge 8 sorted-8 keys -> 16th smallest -> tau ----------
    const int rowA = qLocal * 68 + split * 8;
#pragma unroll
    for (int t = 0; t < 8; ++t) bufA[rowA + t] = tk[t];
    __syncthreads();

    if (split < 4) {
        const unsigned* sa = bufA + qLocal * 68 + split * 16;
        unsigned* dst = bufB + qLocal * 68 + split * 16;
        MRGU(sa, sa + 8, 8, dst[r] = o);
    }
    __syncthreads();
    if (split < 2) {
        const unsigned* sa = bufB + qLocal * 68 + split * 32;
        unsigned* dst = bufA + qLocal * 68 + split * 16;
        MRGU(sa, sa + 16, 16, dst[r] = o);
    }
    __syncthreads();
    if (split == 0) {
        const unsigned* sa = bufA + qLocal * 68;
        unsigned last = 0;
        MRGU(sa, sa + 16, 16, last = o);
        tau_sm[qLocal] = last | 0x7FFu;    // bin-top: upper bound of sample d16
    }
    __syncthreads();
    const float tauf = __uint_as_float(tau_sm[qLocal]);

    // ---------- block stats: center + prune radius ----------
    if (split == 0) {
        sx[qLocal] = qx; sy[qLocal] = qy; sz[qLocal] = qz;
        st[qLocal] = sqrtf(fmaxf(tauf, 0.0f));
    }
    __syncthreads();
    if (tid < 32) {
        float mnx = fminf(sx[tid], sx[tid + 32]), mxx = fmaxf(sx[tid], sx[tid + 32]);
        float mny = fminf(sy[tid], sy[tid + 32]), mxy = fmaxf(sy[tid], sy[tid + 32]);
        float mnz = fminf(sz[tid], sz[tid + 32]), mxz = fmaxf(sz[tid], sz[tid + 32]);
        float mst = fmaxf(st[tid], st[tid + 32]);
#pragma unroll
        for (int o = 16; o; o >>= 1) {
            mnx = fminf(mnx, __shfl_xor_sync(0xffffffffu, mnx, o));
            mxx = fmaxf(mxx, __shfl_xor_sync(0xffffffffu, mxx, o));
            mny = fminf(mny, __shfl_xor_sync(0xffffffffu, mny, o));
            mxy = fmaxf(mxy, __shfl_xor_sync(0xffffffffu, mxy, o));
            mnz = fminf(mnz, __shfl_xor_sync(0xffffffffu, mnz, o));
            mxz = fmaxf(mxz, __shfl_xor_sync(0xffffffffu, mxz, o));
            mst = fmaxf(mst, __shfl_xor_sync(0xffffffffu, mst, o));
        }
        const float cx0 = 0.5f * (mnx + mxx);
        const float cy0 = 0.5f * (mny + mxy);
        const float cz0 = 0.5f * (mnz + mxz);
        float dx1 = sx[tid] - cx0, dy1 = sy[tid] - cy0, dz1 = sz[tid] - cz0;
        float r1 = sqrtf(fmaf(dz1, dz1, fmaf(dy1, dy1, dx1 * dx1)));
        float dx2 = sx[tid + 32] - cx0, dy2 = sy[tid + 32] - cy0, dz2 = sz[tid + 32] - cz0;
        float r2 = sqrtf(fmaf(dz2, dz2, fmaf(dy2, dy2, dx2 * dx2)));
        float rb = fmaxf(r1, r2);
#pragma unroll
        for (int o = 16; o; o >>= 1)
            rb = fmaxf(rb, __shfl_xor_sync(0xffffffffu, rb, o));
        if (tid == 0) {
            float pr = rb + mst + 0.01f;
            statf[0] = cx0; statf[1] = cy0; statf[2] = cz0; statf[3] = pr * pr;
        }
    }
    __syncthreads();
    const float cx0 = statf[0], cy0 = statf[1], cz0 = statf[2];
    const float pruneR2 = statf[3];

    // ---------- Phase B: stage + block-prune + per-query filter ----------
    int cnt = 0;
    unsigned* seg = &g_survk[gq][split][0];
    const int lane = tid & 31, wid = tid >> 5;

#pragma unroll 1
    for (int pass = 0; pass < 2; ++pass) {
        __syncthreads();                   // prior consumers of stage/compact done
        const int wbase = pass * PASS_CANDS;
        int kcnt = 0;
        unsigned kmask = 0;
#pragma unroll
        for (int k = 0; k < 8; ++k) {
            const int i = tid + k * KTH;
            const int jg = wbase + i;
            float x = cb[3 * jg], y = cb[3 * jg + 1], z = cb[3 * jg + 2];
            float w = fmaf(x, x, fmaf(y, y, z * z));
            xs[i] = x; ys[i] = y; zs[i] = z; ws[i] = w;
            float dx = x - cx0, dy = y - cy0, dz = z - cz0;
            float dc2 = fmaf(dz, dz, fmaf(dy, dy, dx * dx));
            bool keep = (dc2 <= pruneR2);
            kmask |= ((unsigned)keep) << k;
            kcnt += (int)keep;
        }
        // deterministic block scan of keep counts
        int incl = kcnt;
#pragma unroll
        for (int o = 1; o < 32; o <<= 1) {
            int n = __shfl_up_sync(0xffffffffu, incl, o);
            if (lane >= o) incl += n;
        }
        if (lane == 31) wsS[wid] = incl;
        __syncthreads();
        if (wid == 0) {
            int s = (lane < 16) ? wsS[lane] : 0;
#pragma unroll
            for (int o = 1; o < 16; o <<= 1) {
                int n = __shfl_up_sync(0xffffffffu, s, o);
                if (lane >= o) s += n;
            }
            if (lane < 16) wsS[lane] = s;
            if (lane == 15) kcS[0] = s;
        }
        __syncthreads();
        const int Kc = kcS[0];

        if (Kc <= CCAP) {
            int off = (wid ? wsS[wid - 1] : 0) + incl - kcnt;
#pragma unroll
            for (int k = 0; k < 8; ++k) {
                if ((kmask >> k) & 1u) {
                    const int i = tid + k * KTH;
                    ccx[off] = xs[i]; ccy[off] = ys[i];
                    ccz[off] = zs[i]; ccw[off] = ws[i];
                    cidx[off] = wbase + i;
                    ++off;
                }
            }
            if (tid == 0) {
                const int Kcp = (Kc + 31) & ~31;
                for (int j = Kc; j < Kcp; ++j) {
                    ccx[j] = 0.0f; ccy[j] = 0.0f; ccz[j] = 0.0f;
                    ccw[j] = 3.0e38f; cidx[j] = 0;
                }
            }
            __syncthreads();
            const int slice = ((Kc + 31) & ~31) >> 3;   // multiple of 4
            const int j0b = split * slice;
#pragma unroll 1
            for (int j0 = j0b; j0 < j0b + slice; j0 += 4) {
                float dv[4];
                dist4s(ccx, ccy, ccz, ccw, j0, ax, ay, az, qw, dv);
#pragma unroll
                for (int i = 0; i < 4; ++i) {
                    if (dv[i] <= tauf) {
                        if (cnt < SCAP)
                            seg[cnt] = (__float_as_uint(dv[i]) & 0x7FFFE000u)
                                     | (unsigned)cidx[j0 + i];
                        ++cnt;
                    }
                }
            }
        } else {
            // overflow: full per-split scan of staged window (proven old path)
            const int gbase = wbase + sbase;
#pragma unroll 2
            for (int j0 = 0; j0 < 512; j0 += 4) {
                float dv[4];
                dist4s(xs, ys, zs, ws, sbase + j0, ax, ay, az, qw, dv);
#pragma unroll
                for (int i = 0; i < 4; ++i) {
                    if (dv[i] <= tauf) {
                        if (cnt < SCAP)
                            seg[cnt] = (__float_as_uint(dv[i]) & 0x7FFFE000u)
                                     | (unsigned)(gbase + j0 + i);
                        ++cnt;
                    }
                }
            }
        }
    }
    g_cnt[gq][split] = cnt;
}

// ====== select: top-16 of survivors (8 threads/query) + fused losses ======
extern "C" __global__ void __launch_bounds__(KTH, 1)
select_kernel(const float* __restrict__ scores, const float* __restrict__ coords) {
    extern __shared__ unsigned char sraw[];
    unsigned* bufA = (unsigned*)sraw;              // [QPB][136]
    unsigned* bufB = bufA + QPB * 136;             // [QPB][68]
    int* ovf = (int*)(bufB + QPB * 68);            // [QPB]
    __shared__ double red[16][6];

    const int tid = threadIdx.x;
    const int qLocal = tid & (QPB - 1);
    const int split = tid >> 6;
    const int gq = blockIdx.x * QPB + qLocal;
    const int goff = (gq >> 13) << 13;

    if (split == 0) ovf[qLocal] = 0;
    __syncthreads();

    int cn = g_cnt[gq][split];
    if (cn > SCAP) { ovf[qLocal] = 1; cn = SCAP; }
    const unsigned* seg = &g_survk[gq][split][0];

    unsigned tk[16];
#pragma unroll
    for (int t = 0; t < 16; ++t) tk[t] = 0xFFFFFFFFu;

#pragma unroll 1
    for (int k = 0; k < cn; k += 8) {
        unsigned bk[8];
#pragma unroll
        for (int i = 0; i < 8; ++i)
            bk[i] = (k + i < cn) ? seg[k + i] : 0xFFFFFFFFu;
        sort8(bk);
#pragma unroll
        for (int i = 0; i < 8; ++i) tk[15 - i] = min(tk[15 - i], bk[i]);
        clean16(tk);
    }

    const int rowA = qLocal * 136 + split * 16;
#pragma unroll
    for (int t = 0; t < 16; ++t) bufA[rowA + t] = tk[t];
    __syncthreads();

    if (split < 4) {
        const unsigned* sa = bufA + qLocal * 136 + split * 32;
        unsigned* dst = bufB + qLocal * 68 + split * 16;
        MRGU(sa, sa + 16, 16, dst[r] = o);
    }
    __syncthreads();
    if (split < 2) {
        const unsigned* sa = bufB + qLocal * 68 + split * 32;
        unsigned* dst = bufA + qLocal * 136 + split * 16;
        MRGU(sa, sa + 16, 16, dst[r] = o);
    }
    __syncthreads();

    double acc[6] = {0, 0, 0, 0, 0, 0};
    if (split == 0) {
        int* out = g_knn + (size_t)gq * KF;
        const unsigned* sa = bufA + qLocal * 136;
        unsigned* nbrow = bufB + qLocal * 68;
        MRGU(sa, sa + 16, 16, {
            unsigned gi = o & 0x1FFFu;
            out[r] = goff + (int)gi;
            nbrow[r] = gi;
        });
        if (ovf[qLocal]) {
            int slot = atomicAdd(&g_nflag, 1);
            g_flagq[slot] = gq;
        } else {
            const float si = scores[gq];
            const float xi = coords[3 * gq], yi = coords[3 * gq + 1], zi = coords[3 * gq + 2];
            float nsum = 0.0f;
#pragma unroll
            for (int r = 0; r < KF; ++r) {
                const int n = goff + (int)nbrow[r];
                const float sn = scores[n];
                const float sd = fabsf(si - sn);
                const float x = (1.0f - sd) * 2.0f;
                const float sig = 1.0f / (1.0f + expf(-x));
                if (r < KN) {
                    const float dx = xi - coords[3 * n];
                    const float dy = yi - coords[3 * n + 1];
                    const float dz = zi - coords[3 * n + 2];
                    const float dist = sqrtf(dx * dx + dy * dy + dz * dz);
                    const float w = expf(-dist * 10.0f);
                    acc[0] += (double)(w * sd * sd);
                    acc[1] += (double)w;
                    acc[2] += (double)logf(sig + 1e-8f);
                    nsum += sn;
                } else {
                    acc[3] += (double)logf(1.0f - sig + 1e-8f);
                }
            }
            const float dm = si - nsum * 0.125f;
            acc[4] = (double)(dm * dm);

            const int cloud = gq >> 13;
            const int local = gq & (Mc - 1);
            int b = (int)(si * (float)NB);
            b = b < 0 ? 0 : (b > NB - 1 ? NB - 1 : b);
            int hcnt = g_hist[cloud][b];
            hcnt = hcnt > BCAP ? BCAP : hcnt;
            int rk = 0;
            const int* mem = &g_members[cloud][b * BCAP];
            for (int k = 0; k < hcnt; ++k) {
                const int m = mem[k];
                const float sm = scores[(cloud << 13) + m];
                rk += (sm < si) || (sm == si && m < local);
            }
            const int rank = g_pref[cloud][b] + rk;
            const float df = si - (float)rank * (1.0f / (float)(Mc - 1));
            acc[5] = (double)(df * df);
        }
    }

    const int lane = threadIdx.x & 31;
    const int wid = threadIdx.x >> 5;
#pragma unroll
    for (int k = 0; k < 6; ++k)
#pragma unroll
        for (int o = 16; o; o >>= 1)
            acc[k] += __shfl_down_sync(0xffffffffu, acc[k], o);
    if (lane == 0)
#pragma unroll
        for (int k = 0; k < 6; ++k) red[wid][k] = acc[k];
    __syncthreads();
    if (wid == 0 && lane < 6) {
        double s = 0.0;
#pragma unroll
        for (int w = 0; w < 16; ++w) s += red[w][lane];
        atomicAdd(&g_acc[lane], s);
    }
}

// ============ exact fallback for overflowed queries (rare) + loss ============
#define FB_BLOCKS 296
#define FB_WARPS 8
__global__ void __launch_bounds__(FB_WARPS * 32)
fallback_kernel(const float* __restrict__ coords, const float* __restrict__ scores) {
    __shared__ unsigned S[FB_WARPS][32][17];
    const int w = threadIdx.x >> 5;
    const int lane = threadIdx.x & 31;
    const int nf = g_nflag;

    for (int f = blockIdx.x * FB_WARPS + w; f < nf; f += FB_BLOCKS * FB_WARPS) {
        const int gq = g_flagq[f];
        const int cloud = gq >> 13;
        const int q = gq & (Mc - 1);
        const float* cb = coords + (size_t)cloud * Mc * 3;
        const float4* cp = (const float4*)cb;
        const float qx = cb[3 * q], qy = cb[3 * q + 1], qz = cb[3 * q + 2];

        unsigned tk[16];
#pragma unroll
        for (int t = 0; t < 16; ++t) tk[t] = 0xFFFFFFFFu;

#pragma unroll 1
        for (int b = 0; b < 32; ++b) {
            const int j0 = lane * 256 + b * 8;
            const float4* p = cp + ((3 * j0) >> 2);
            float4 A = p[0], Bv = p[1], C = p[2], D = p[3], E = p[4], F = p[5];
            float x8[8] = {A.x, A.w, Bv.z, C.y, D.x, D.w, E.z, F.y};
            float y8[8] = {A.y, Bv.x, Bv.w, C.z, D.y, E.x, E.w, F.z};
            float z8[8] = {A.z, Bv.y, C.x, C.w, D.z, E.y, F.x, F.w};
            unsigned bk[8];
#pragma unroll
            for (int i = 0; i < 8; ++i) {
                float dx = x8[i] - qx, dy = y8[i] - qy, dz = z8[i] - qz;
                float d = fmaf(dz, dz, fmaf(dy, dy, dx * dx));
                bk[i] = (__float_as_uint(d) & 0xFFFFE000u) | (unsigned)(j0 + i);
            }
            sort8(bk);
#pragma unroll
            for (int i = 0; i < 8; ++i) tk[15 - i] = min(tk[15 - i], bk[i]);
            clean16(tk);
        }

#pragma unroll
        for (int t = 0; t < 16; ++t) S[w][lane][t] = tk[t];
        __syncwarp();
#pragma unroll
        for (int s = 1; s < 32; s <<= 1) {
            if ((lane & (2 * s - 1)) == 0) {
                unsigned ok[16];
#pragma unroll
                for (int t = 0; t < 16; ++t) ok[t] = S[w][lane + s][t];
#pragma unroll
                for (int t = 0; t < 16; ++t) tk[t] = min(tk[t], ok[15 - t]);
                clean16(tk);
#pragma unroll
                for (int t = 0; t < 16; ++t) S[w][lane][t] = tk[t];
            }
            __syncwarp();
        }
        if (lane == 0) {
            int* out = g_knn + (size_t)gq * KF;
            const int goff = cloud * Mc;
#pragma unroll
            for (int t = 0; t < 16; ++t) out[t] = goff + (int)(tk[t] & 0x1FFFu);

            double acc[6] = {0, 0, 0, 0, 0, 0};
            const float si = scores[gq];
            const float xi = cb[3 * q], yi = cb[3 * q + 1], zi = cb[3 * q + 2];
            float nsum = 0.0f;
#pragma unroll
            for (int r = 0; r < KF; ++r) {
                const int n = goff + (int)(tk[r] & 0x1FFFu);
                const float sn = scores[n];
                const float sd = fabsf(si - sn);
                const float x = (1.0f - sd) * 2.0f;
                const float sig = 1.0f / (1.0f + expf(-x));
                if (r < KN) {
                    const float dx = xi - coords[3 * n];
                    const float dy = yi - coords[3 * n + 1];
                    const float dz = zi - coords[3 * n + 2];
                    const float dist = sqrtf(dx * dx + dy * dy + dz * dz);
                    const float wv = expf(-dist * 10.0f);
                    acc[0] += (double)(wv * sd * sd);
                    acc[1] += (double)wv;
                    acc[2] += (double)logf(sig + 1e-8f);
                    nsum += sn;
                } else {
                    acc[3] += (double)logf(1.0f - sig + 1e-8f);
                }
            }
            const float dm = si - nsum * 0.125f;
            acc[4] = (double)(dm * dm);

            int b = (int)(si * (float)NB);
            b = b < 0 ? 0 : (b > NB - 1 ? NB - 1 : b);
            int hcnt = g_hist[cloud][b];
            hcnt = hcnt > BCAP ? BCAP : hcnt;
            int rk = 0;
            const int* mem = &g_members[cloud][b * BCAP];
            for (int k = 0; k < hcnt; ++k) {
                const int m = mem[k];
                const float sm = scores[(cloud << 13) + m];
                rk += (sm < si) || (sm == si && m < q);
            }
            const int rank = g_pref[cloud][b] + rk;
            const float df = si - (float)rank * (1.0f / (float)(Mc - 1));
            acc[5] = (double)(df * df);
#pragma unroll
            for (int k = 0; k < 6; ++k) atomicAdd(&g_acc[k], acc[k]);
        }
        __syncwarp();
    }
}

// ================= zero =================
__global__ void zero_kernel() {
    const int t = blockIdx.x * blockDim.x + threadIdx.x;
    if (t < 8) g_acc[t] = 0.0;
    if (t == 8) g_nflag = 0;
    const int total = Bc * NB + 2 * Bc * NCELL;
    for (int i = t; i < total; i += gridDim.x * blockDim.x) {
        if (i < Bc * NB) ((int*)g_hist)[i] = 0;
        else if (i < Bc * NB + Bc * NCELL) ((int*)g_chist)[i - Bc * NB] = 0;
        else ((int*)g_cfill)[i - Bc * NB - Bc * NCELL] = 0;
    }
}

// ============ rank bucketing + cell histogram (fused per-point pass) ============
__global__ void rank_cell_build(const float* __restrict__ scores,
                                const float* __restrict__ coords) {
    const int i = blockIdx.x * blockDim.x + threadIdx.x;
    if (i >= Nc) return;
    const int cloud = i >> 13;
    const int local = i & (Mc - 1);
    const float s = scores[i];
    int b = (int)(s * (float)NB);
    b = b < 0 ? 0 : (b > NB - 1 ? NB - 1 : b);
    const int slot = atomicAdd(&g_hist[cloud][b], 1);
    if (slot < BCAP) g_members[cloud][b * BCAP + slot] = local;

    const unsigned code = morton_of(coords[3 * i], coords[3 * i + 1], coords[3 * i + 2]);
    atomicAdd(&g_chist[cloud][code], 1);
}

__global__ void prefix_kernel() {       // scores hist: 4096 per cloud
    __shared__ int sc[1024];
    const int cloud = blockIdx.x;
    const int t = threadIdx.x;
    const int base = t * 4;
    int h0 = g_hist[cloud][base + 0];
    int h1 = g_hist[cloud][base + 1];
    int h2 = g_hist[cloud][base + 2];
    int h3 = g_hist[cloud][base + 3];
    int sum = h0 + h1 + h2 + h3;
    sc[t] = sum;
    __syncthreads();
    for (int off = 1; off < 1024; off <<= 1) {
        int v = (t >= off) ? sc[t - off] : 0;
        __syncthreads();
        sc[t] += v;
        __syncthreads();
    }
    int excl = sc[t] - sum;
    g_pref[cloud][base + 0] = excl; excl += h0;
    g_pref[cloud][base + 1] = excl; excl += h1;
    g_pref[cloud][base + 2] = excl; excl += h2;
    g_pref[cloud][base + 3] = excl;
}

__global__ void cell_prefix_kernel() {  // cell hist: 32768 per cloud
    __shared__ int sc[1024];
    const int cloud = blockIdx.x;
    const int t = threadIdx.x;
    const int base = t * 32;
    int sum = 0;
#pragma unroll
    for (int j = 0; j < 32; ++j) sum += g_chist[cloud][base + j];
    sc[t] = sum;
    __syncthreads();
    for (int off = 1; off < 1024; off <<= 1) {
        int v = (t >= off) ? sc[t - off] : 0;
        __syncthreads();
        sc[t] += v;
        __syncthreads();
    }
    int excl = sc[t] - sum;
#pragma unroll
    for (int j = 0; j < 32; ++j) {
        g_cpref[cloud][base + j] = excl;
        excl += g_chist[cloud][base + j];
    }
}

__global__ void cell_scatter_kernel(const float* __restrict__ coords) {
    const int i = blockIdx.x * blockDim.x + threadIdx.x;
    if (i >= Nc) return;
    const int cloud = i >> 13;
    const int local = i & (Mc - 1);
    const unsigned code = morton_of(coords[3 * i], coords[3 * i + 1], coords[3 * i + 2]);
    const int pos = g_cpref[cloud][code] + atomicAdd(&g_cfill[cloud][code], 1);
    g_qperm[cloud * Mc + pos] = local;
}

// ================= finalize =================
__global__ void finalize_kernel(float* out) {
    const double l_loc = g_acc[0] / fmax(g_acc[1], 1e-8);
    const double l_pos = -g_acc[2] / (double)((size_t)Nc * KN);
    const double l_neg = -g_acc[3] / (double)((size_t)Nc * KN);
    const double l_con = l_pos + l_neg;
    const double l_smooth = g_acc[4] / (double)Nc;
    const double l_dist = g_acc[5] / (double)Nc;
    out[0] = (float)(1.0 * l_loc + 0.5 * l_con + 0.3 * l_dist + 0.2 * l_smooth);
}

extern "C" void kernel_launch(void* const* d_in, const int* in_sizes, int n_in,
                              void* d_out, int out_size) {
    const float* scores = (const float*)d_in[0];
    const float* coords = (const float*)d_in[1];
    (void)in_sizes; (void)n_in; (void)out_size;

    cudaFuncSetAttribute(knn_kernel,
                         cudaFuncAttributeMaxDynamicSharedMemorySize, SM_KNN_TOTAL);
    const int SEL_SMEM = (QPB * 136 + QPB * 68) * (int)sizeof(unsigned)
                       + QPB * (int)sizeof(int);
    cudaFuncSetAttribute(select_kernel,
                         cudaFuncAttributeMaxDynamicSharedMemorySize, SEL_SMEM);

    zero_kernel<<<32, 1024>>>();
    rank_cell_build<<<Nc / 256, 256>>>(scores, coords);
    prefix_kernel<<<Bc, 1024>>>();
    cell_prefix_kernel<<<Bc, 1024>>>();
    cell_scatter_kernel<<<Nc / 256, 256>>>(coords);
    knn_kernel<<<Bc * QBLKS, KTH, SM_KNN_TOTAL>>>(coords);
    select_kernel<<<Nc / QPB, KTH, SEL_SMEM>>>(scores, coords);
    fallback_kernel<<<FB_BLOCKS, FB_WARPS * 32>>>(coords, scores);
    finalize_kernel<<<1, 1>>>((float*)d_out);
}

// round 15
// speedup vs baseline: 1.3406x; 1.3406x over previous
#include <cuda_runtime.h>
#include <math.h>
#include <float.h>

#define Bc 2
#define Mc 8192
#define Nc (Bc * Mc)
#define KF 16
#define KN 8
#define NB 4096
#define BCAP 64
#define NCELL 4096              // 16^3 morton cells

#define QPB 64                  // queries per block (knn/select)
#define SPLITS 8
#define KTH 512
#define QBLKS 128               // per cloud; knn grid = 256
#define PASS_CANDS 4096         // candidates staged per pass (64KB SoA)
#define SCAP 64                 // survivor cap per (query, slice)
#define CCAP 2048               // compacted-candidate cap per window
#define CPAD (CCAP + 32)

// ---- scratch (device globals; no allocation allowed) ----
__device__ int      g_knn[(size_t)Nc * KF];
__device__ double   g_acc[8];
__device__ int      g_hist[Bc][NB];
__device__ int      g_pref[Bc][NB];
__device__ int      g_members[Bc][NB * BCAP];
__device__ int      g_nflag;
__device__ int      g_flagq[Nc];
__device__ unsigned g_survk[Nc][SPLITS][SCAP];  // (d18)<<13 | idx13
__device__ int      g_cnt[Nc][SPLITS];
__device__ int      g_chist[Bc][NCELL];
__device__ int      g_cpref[Bc][NCELL];
__device__ int      g_cfill[Bc][NCELL];
__device__ int      g_qperm[Bc * Mc];

// ----- u32 compare-exchange: a=min, b=max -----
__device__ __forceinline__ void cx(unsigned& a, unsigned& b) {
    unsigned lo = min(a, b);
    b = max(a, b);
    a = lo;
}

__device__ __forceinline__ void sort8(unsigned k[8]) {
    cx(k[0],k[1]); cx(k[2],k[3]); cx(k[4],k[5]); cx(k[6],k[7]);
    cx(k[0],k[2]); cx(k[1],k[3]); cx(k[4],k[6]); cx(k[5],k[7]);
    cx(k[1],k[2]); cx(k[5],k[6]);
    cx(k[0],k[4]); cx(k[1],k[5]); cx(k[2],k[6]); cx(k[3],k[7]);
    cx(k[2],k[4]); cx(k[3],k[5]);
    cx(k[1],k[2]); cx(k[3],k[4]); cx(k[5],k[6]);
}

__device__ __forceinline__ void clean8(unsigned k[8]) {
    cx(k[0],k[4]); cx(k[1],k[5]); cx(k[2],k[6]); cx(k[3],k[7]);
    cx(k[0],k[2]); cx(k[1],k[3]); cx(k[4],k[6]); cx(k[5],k[7]);
    cx(k[0],k[1]); cx(k[2],k[3]); cx(k[4],k[5]); cx(k[6],k[7]);
}

__device__ __forceinline__ void clean16(unsigned k[16]) {
#pragma unroll
    for (int j = 8; j; j >>= 1)
#pragma unroll
        for (int i = 0; i < 16; ++i) {
            int l = i ^ j;
            if (l > i) cx(k[i], k[l]);
        }
}

#define MRGU(SRC_A, SRC_B, LEN, DSTSTMT)                                      \
    {                                                                         \
        int ii = 0, jj = 0;                                                   \
        _Pragma("unroll 1")                                                   \
        for (int r = 0; r < 16; ++r) {                                        \
            unsigned a = (SRC_A)[min(ii, (LEN) - 1)];                         \
            unsigned b = (SRC_B)[min(jj, (LEN) - 1)];                         \
            bool takeA = (jj >= (LEN)) || ((ii < (LEN)) && (a <= b));         \
            unsigned o = takeA ? a : b;                                       \
            ii += takeA; jj += !takeA;                                        \
            DSTSTMT;                                                          \
        }                                                                     \
    }

// 4 distances from SoA via float4 loads: d = ax*x + ay*y + az*z + (w + qw)
__device__ __forceinline__ void dist4s(const float* __restrict__ xs,
                                       const float* __restrict__ ys,
                                       const float* __restrict__ zs,
                                       const float* __restrict__ ws, int j0,
                                       float ax, float ay, float az, float qw,
                                       float d[4]) {
    float4 X = *(const float4*)(xs + j0);
    float4 Y = *(const float4*)(ys + j0);
    float4 Z = *(const float4*)(zs + j0);
    float4 W = *(const float4*)(ws + j0);
    d[0] = fmaf(ax, X.x, fmaf(ay, Y.x, fmaf(az, Z.x, W.x + qw)));
    d[1] = fmaf(ax, X.y, fmaf(ay, Y.y, fmaf(az, Z.y, W.y + qw)));
    d[2] = fmaf(ax, X.z, fmaf(ay, Y.z, fmaf(az, Z.z, W.z + qw)));
    d[3] = fmaf(ax, X.w, fmaf(ay, Y.w, fmaf(az, Z.w, W.w + qw)));
}

// Morton bit expansion (10-bit safe; used with 4 bits)
__device__ __forceinline__ unsigned expand3(unsigned v) {
    v &= 0x3FFu;
    v = (v | (v << 16)) & 0x030000FFu;
    v = (v | (v << 8))  & 0x0300F00Fu;
    v = (v | (v << 4))  & 0x030C30C3u;
    v = (v | (v << 2))  & 0x09249249u;
    return v;
}
__device__ __forceinline__ unsigned morton_of(float x, float y, float z) {
    int mx = min(15, max(0, (int)(x + 8.0f)));
    int my = min(15, max(0, (int)(y + 8.0f)));
    int mz = min(15, max(0, (int)(z + 8.0f)));
    return expand3((unsigned)mx) | (expand3((unsigned)my) << 1)
         | (expand3((unsigned)mz) << 2);
}

// ---- knn smem layout (byte offsets) ----
#define SM_STAGE   0                         // 4 arrays x 4096 x 4 = 65536
#define SM_COMPACT 65536                     // 5 arrays x CPAD x 4 = 41600
#define SM_TAU     (SM_COMPACT + CPAD * 5 * 4)   // 107136; 64 x u32
#define SM_SX      (SM_TAU + 256)
#define SM_SY      (SM_SX + 256)
#define SM_SZ      (SM_SY + 256)
#define SM_ST      (SM_SZ + 256)
#define SM_STATF   (SM_ST + 256)             // 4 floats
#define SM_KC      (SM_STATF + 16)           // 1 int
#define SM_WSUM    (SM_KC + 16)              // 16 ints
#define SM_KNN_TOTAL (SM_WSUM + 64)          // 108512

// ================= Kernel A: tau + block-pruned filter =================
extern "C" __global__ void __launch_bounds__(KTH, 2)
knn_kernel(const float* __restrict__ coords) {
    extern __shared__ unsigned char sraw[];
    float* xs = (float*)(sraw + SM_STAGE);
    float* ys = xs + PASS_CANDS;
    float* zs = ys + PASS_CANDS;
    float* ws = zs + PASS_CANDS;
    float* ccx = (float*)(sraw + SM_COMPACT);
    float* ccy = ccx + CPAD;
    float* ccz = ccy + CPAD;
    float* ccw = ccz + CPAD;
    int*   cidx = (int*)(ccw + CPAD);
    unsigned* bufA = (unsigned*)(sraw + SM_COMPACT);   // overlay (pre-Phase-B)
    unsigned* bufB = bufA + QPB * 68;
    unsigned* tau_sm = (unsigned*)(sraw + SM_TAU);
    float* sx = (float*)(sraw + SM_SX);
    float* sy = (float*)(sraw + SM_SY);
    float* sz = (float*)(sraw + SM_SZ);
    float* st = (float*)(sraw + SM_ST);
    float* statf = (float*)(sraw + SM_STATF);
    int*   kcS = (int*)(sraw + SM_KC);
    int*   wsS = (int*)(sraw + SM_WSUM);

    const int tid = threadIdx.x;
    const int cloud = blockIdx.x >> 7;
    const int qblk = blockIdx.x & 127;
    const int qLocal = tid & (QPB - 1);
    const int split = tid >> 6;            // warp-uniform

    const float* cb = coords + (size_t)cloud * Mc * 3;
    const float4* cp = (const float4*)cb;
    const int q = g_qperm[cloud * Mc + qblk * QPB + qLocal];
    const int gq = cloud * Mc + q;

    const float qx = cb[3 * q], qy = cb[3 * q + 1], qz = cb[3 * q + 2];
    const float qw = fmaf(qx, qx, fmaf(qy, qy, qz * qz));
    const float ax = -2.0f * qx, ay = -2.0f * qy, az = -2.0f * qz;
    const int sbase = split << 9;

    // ---------- Phase A: keep-8 over 512-point sample, direct uniform LDG ----------
    unsigned tk[8];
#pragma unroll
    for (int t = 0; t < 8; ++t) tk[t] = 0xFFFFFFFFu;

#pragma unroll 1
    for (int b = 0; b < 8; ++b) {
        const int j0 = (b < 4) ? (sbase + b * 8)
                               : (PASS_CANDS + sbase + (b - 4) * 8);
        const float4* p = cp + ((3 * j0) >> 2);   // j0 % 8 == 0 -> aligned
        float4 A = p[0], Bv = p[1], C = p[2], D = p[3], E = p[4], F = p[5];
        float x8[8] = {A.x, A.w, Bv.z, C.y, D.x, D.w, E.z, F.y};
        float y8[8] = {A.y, Bv.x, Bv.w, C.z, D.y, E.x, E.w, F.z};
        float z8[8] = {A.z, Bv.y, C.x, C.w, D.z, E.y, F.x, F.w};
        unsigned bk[8];
#pragma unroll
        for (int i = 0; i < 8; ++i) {
            float w = fmaf(x8[i], x8[i], fmaf(y8[i], y8[i], z8[i] * z8[i]));
            float d = fmaf(ax, x8[i], fmaf(ay, y8[i], fmaf(az, z8[i], w + qw)));
            bk[i] = __float_as_uint(d) & 0x7FFFF800u;
        }
        sort8(bk);
#pragma unroll
        for (int i = 0; i < 8; ++i) tk[i] = min(tk[i], bk[7 - i]);
        clean8(tk);
    }

    // ---------- merge 8 sorted-8 keys -> 16th smallest -> tau ----------
    const int rowA = qLocal * 68 + split * 8;
#pragma unroll
    for (int t = 0; t < 8; ++t) bufA[rowA + t] = tk[t];
    __syncthreads();

    if (split < 4) {
        const unsigned* sa = bufA + qLocal * 68 + split * 16;
        unsigned* dst = bufB + qLocal * 68 + split * 16;
        MRGU(sa, sa + 8, 8, dst[r] = o);
    }
    __syncthreads();
    if (split < 2) {
        const unsigned* sa = bufB + qLocal * 68 + split * 32;
        unsigned* dst = bufA + qLocal * 68 + split * 16;
        MRGU(sa, sa + 16, 16, dst[r] = o);
    }
    __syncthreads();
    if (split == 0) {
        const unsigned* sa = bufA + qLocal * 68;
        unsigned last = 0;
        MRGU(sa, sa + 16, 16, last = o);
        tau_sm[qLocal] = last | 0x7FFu;    // bin-top: upper bound of sample d16
    }
    __syncthreads();
    const float tauf = __uint_as_float(tau_sm[qLocal]);

    // ---------- block stats: center + prune radius ----------
    if (split == 0) {
        sx[qLocal] = qx; sy[qLocal] = qy; sz[qLocal] = qz;
        st[qLocal] = sqrtf(fmaxf(tauf, 0.0f));
    }
    __syncthreads();
    if (tid < 32) {
        float mnx = fminf(sx[tid], sx[tid + 32]), mxx = fmaxf(sx[tid], sx[tid + 32]);
        float mny = fminf(sy[tid], sy[tid + 32]), mxy = fmaxf(sy[tid], sy[tid + 32]);
        float mnz = fminf(sz[tid], sz[tid + 32]), mxz = fmaxf(sz[tid], sz[tid + 32]);
        float mst = fmaxf(st[tid], st[tid + 32]);
#pragma unroll
        for (int o = 16; o; o >>= 1) {
            mnx = fminf(mnx, __shfl_xor_sync(0xffffffffu, mnx, o));
            mxx = fmaxf(mxx, __shfl_xor_sync(0xffffffffu, mxx, o));
            mny = fminf(mny, __shfl_xor_sync(0xffffffffu, mny, o));
            mxy = fmaxf(mxy, __shfl_xor_sync(0xffffffffu, mxy, o));
            mnz = fminf(mnz, __shfl_xor_sync(0xffffffffu, mnz, o));
            mxz = fmaxf(mxz, __shfl_xor_sync(0xffffffffu, mxz, o));
            mst = fmaxf(mst, __shfl_xor_sync(0xffffffffu, mst, o));
        }
        const float cx0 = 0.5f * (mnx + mxx);
        const float cy0 = 0.5f * (mny + mxy);
        const float cz0 = 0.5f * (mnz + mxz);
        float dx1 = sx[tid] - cx0, dy1 = sy[tid] - cy0, dz1 = sz[tid] - cz0;
        float r1 = sqrtf(fmaf(dz1, dz1, fmaf(dy1, dy1, dx1 * dx1)));
        float dx2 = sx[tid + 32] - cx0, dy2 = sy[tid + 32] - cy0, dz2 = sz[tid + 32] - cz0;
        float r2 = sqrtf(fmaf(dz2, dz2, fmaf(dy2, dy2, dx2 * dx2)));
        float rb = fmaxf(r1, r2);
#pragma unroll
        for (int o = 16; o; o >>= 1)
            rb = fmaxf(rb, __shfl_xor_sync(0xffffffffu, rb, o));
        if (tid == 0) {
            float pr = rb + mst + 0.01f;
            statf[0] = cx0; statf[1] = cy0; statf[2] = cz0; statf[3] = pr * pr;
        }
    }
    __syncthreads();
    const float cx0 = statf[0], cy0 = statf[1], cz0 = statf[2];
    const float pruneR2 = statf[3];

    // ---------- Phase B: stage + block-prune + per-query filter ----------
    int cnt = 0;
    unsigned* seg = &g_survk[gq][split][0];
    const int lane = tid & 31, wid = tid >> 5;

#pragma unroll 1
    for (int pass = 0; pass < 2; ++pass) {
        __syncthreads();                   // prior consumers of stage/compact done
        const int wbase = pass * PASS_CANDS;
        int kcnt = 0;
        unsigned kmask = 0;
#pragma unroll
        for (int k = 0; k < 8; ++k) {
            const int i = tid + k * KTH;
            const int jg = wbase + i;
            float x = cb[3 * jg], y = cb[3 * jg + 1], z = cb[3 * jg + 2];
            float w = fmaf(x, x, fmaf(y, y, z * z));
            xs[i] = x; ys[i] = y; zs[i] = z; ws[i] = w;
            float dx = x - cx0, dy = y - cy0, dz = z - cz0;
            float dc2 = fmaf(dz, dz, fmaf(dy, dy, dx * dx));
            bool keep = (dc2 <= pruneR2);
            kmask |= ((unsigned)keep) << k;
            kcnt += (int)keep;
        }
        // deterministic block scan of keep counts
        int incl = kcnt;
#pragma unroll
        for (int o = 1; o < 32; o <<= 1) {
            int n = __shfl_up_sync(0xffffffffu, incl, o);
            if (lane >= o) incl += n;
        }
        if (lane == 31) wsS[wid] = incl;
        __syncthreads();
        if (wid == 0) {
            int s = (lane < 16) ? wsS[lane] : 0;
#pragma unroll
            for (int o = 1; o < 16; o <<= 1) {
                int n = __shfl_up_sync(0xffffffffu, s, o);
                if (lane >= o) s += n;
            }
            if (lane < 16) wsS[lane] = s;
            if (lane == 15) kcS[0] = s;
        }
        __syncthreads();
        const int Kc = kcS[0];

        if (Kc <= CCAP) {
            int off = (wid ? wsS[wid - 1] : 0) + incl - kcnt;
#pragma unroll
            for (int k = 0; k < 8; ++k) {
                if ((kmask >> k) & 1u) {
                    const int i = tid + k * KTH;
                    ccx[off] = xs[i]; ccy[off] = ys[i];
                    ccz[off] = zs[i]; ccw[off] = ws[i];
                    cidx[off] = wbase + i;
                    ++off;
                }
            }
            if (tid == 0) {
                const int Kcp = (Kc + 31) & ~31;
                for (int j = Kc; j < Kcp; ++j) {
                    ccx[j] = 0.0f; ccy[j] = 0.0f; ccz[j] = 0.0f;
                    ccw[j] = 3.0e38f; cidx[j] = 0;
                }
            }
            __syncthreads();
            const int slice = ((Kc + 31) & ~31) >> 3;   // multiple of 4
            const int j0b = split * slice;
#pragma unroll 1
            for (int j0 = j0b; j0 < j0b + slice; j0 += 4) {
                float dv[4];
                dist4s(ccx, ccy, ccz, ccw, j0, ax, ay, az, qw, dv);
#pragma unroll
                for (int i = 0; i < 4; ++i) {
                    if (dv[i] <= tauf) {
                        if (cnt < SCAP)
                            seg[cnt] = (__float_as_uint(dv[i]) & 0x7FFFE000u)
                                     | (unsigned)cidx[j0 + i];
                        ++cnt;
                    }
                }
            }
        } else {
            // overflow: full per-split scan of staged window (proven old path)
            const int gbase = wbase + sbase;
#pragma unroll 2
            for (int j0 = 0; j0 < 512; j0 += 4) {
                float dv[4];
                dist4s(xs, ys, zs, ws, sbase + j0, ax, ay, az, qw, dv);
#pragma unroll
                for (int i = 0; i < 4; ++i) {
                    if (dv[i] <= tauf) {
                        if (cnt < SCAP)
                            seg[cnt] = (__float_as_uint(dv[i]) & 0x7FFFE000u)
                                     | (unsigned)(gbase + j0 + i);
                        ++cnt;
                    }
                }
            }
        }
    }
    g_cnt[gq][split] = cnt;
}

// ====== select: top-16 of survivors (8 threads/query) + fused losses ======
extern "C" __global__ void __launch_bounds__(KTH, 1)
select_kernel(const float* __restrict__ scores, const float* __restrict__ coords) {
    extern __shared__ unsigned char sraw[];
    unsigned* bufA = (unsigned*)sraw;              // [QPB][136]
    unsigned* bufB = bufA + QPB * 136;             // [QPB][68]
    int* ovf = (int*)(bufB + QPB * 68);            // [QPB]
    __shared__ double red[16][6];

    const int tid = threadIdx.x;
    const int qLocal = tid & (QPB - 1);
    const int split = tid >> 6;
    const int gq = blockIdx.x * QPB + qLocal;
    const int goff = (gq >> 13) << 13;

    if (split == 0) ovf[qLocal] = 0;
    __syncthreads();

    int cn = g_cnt[gq][split];
    if (cn > SCAP) { ovf[qLocal] = 1; cn = SCAP; }
    const unsigned* seg = &g_survk[gq][split][0];

    unsigned tk[16];
#pragma unroll
    for (int t = 0; t < 16; ++t) tk[t] = 0xFFFFFFFFu;

#pragma unroll 1
    for (int k = 0; k < cn; k += 8) {
        unsigned bk[8];
#pragma unroll
        for (int i = 0; i < 8; ++i)
            bk[i] = (k + i < cn) ? seg[k + i] : 0xFFFFFFFFu;
        sort8(bk);
#pragma unroll
        for (int i = 0; i < 8; ++i) tk[15 - i] = min(tk[15 - i], bk[i]);
        clean16(tk);
    }

    const int rowA = qLocal * 136 + split * 16;
#pragma unroll
    for (int t = 0; t < 16; ++t) bufA[rowA + t] = tk[t];
    __syncthreads();

    if (split < 4) {
        const unsigned* sa = bufA + qLocal * 136 + split * 32;
        unsigned* dst = bufB + qLocal * 68 + split * 16;
        MRGU(sa, sa + 16, 16, dst[r] = o);
    }
    __syncthreads();
    if (split < 2) {
        const unsigned* sa = bufB + qLocal * 68 + split * 32;
        unsigned* dst = bufA + qLocal * 136 + split * 16;
        MRGU(sa, sa + 16, 16, dst[r] = o);
    }
    __syncthreads();

    double acc[6] = {0, 0, 0, 0, 0, 0};
    if (split == 0) {
        int* out = g_knn + (size_t)gq * KF;
        const unsigned* sa = bufA + qLocal * 136;
        unsigned* nbrow = bufB + qLocal * 68;
        MRGU(sa, sa + 16, 16, {
            unsigned gi = o & 0x1FFFu;
            out[r] = goff + (int)gi;
            nbrow[r] = gi;
        });
        if (ovf[qLocal]) {
            int slot = atomicAdd(&g_nflag, 1);
            g_flagq[slot] = gq;
        } else {
            const float si = scores[gq];
            const float xi = coords[3 * gq], yi = coords[3 * gq + 1], zi = coords[3 * gq + 2];
            float nsum = 0.0f;
#pragma unroll
            for (int r = 0; r < KF; ++r) {
                const int n = goff + (int)nbrow[r];
                const float sn = scores[n];
                const float sd = fabsf(si - sn);
                const float x = (1.0f - sd) * 2.0f;
                const float sig = 1.0f / (1.0f + expf(-x));
                if (r < KN) {
                    const float dx = xi - coords[3 * n];
                    const float dy = yi - coords[3 * n + 1];
                    const float dz = zi - coords[3 * n + 2];
                    const float dist = sqrtf(dx * dx + dy * dy + dz * dz);
                    const float w = expf(-dist * 10.0f);
                    acc[0] += (double)(w * sd * sd);
                    acc[1] += (double)w;
                    acc[2] += (double)logf(sig + 1e-8f);
                    nsum += sn;
                } else {
                    acc[3] += (double)logf(1.0f - sig + 1e-8f);
                }
            }
            const float dm = si - nsum * 0.125f;
            acc[4] = (double)(dm * dm);

            const int cloud = gq >> 13;
            const int local = gq & (Mc - 1);
            int b = (int)(si * (float)NB);
            b = b < 0 ? 0 : (b > NB - 1 ? NB - 1 : b);
            int hcnt = g_hist[cloud][b];
            hcnt = hcnt > BCAP ? BCAP : hcnt;
            int rk = 0;
            const int* mem = &g_members[cloud][b * BCAP];
            for (int k = 0; k < hcnt; ++k) {
                const int m = mem[k];
                const float sm = scores[(cloud << 13) + m];
                rk += (sm < si) || (sm == si && m < local);
            }
            const int rank = g_pref[cloud][b] + rk;
            const float df = si - (float)rank * (1.0f / (float)(Mc - 1));
            acc[5] = (double)(df * df);
        }
    }

    const int lane = threadIdx.x & 31;
    const int wid = threadIdx.x >> 5;
#pragma unroll
    for (int k = 0; k < 6; ++k)
#pragma unroll
        for (int o = 16; o; o >>= 1)
            acc[k] += __shfl_down_sync(0xffffffffu, acc[k], o);
    if (lane == 0)
#pragma unroll
        for (int k = 0; k < 6; ++k) red[wid][k] = acc[k];
    __syncthreads();
    if (wid == 0 && lane < 6) {
        double s = 0.0;
#pragma unroll
        for (int w = 0; w < 16; ++w) s += red[w][lane];
        atomicAdd(&g_acc[lane], s);
    }
}

// ============ exact fallback for overflowed queries (rare) + loss ============
#define FB_BLOCKS 296
#define FB_WARPS 8
__global__ void __launch_bounds__(FB_WARPS * 32)
fallback_kernel(const float* __restrict__ coords, const float* __restrict__ scores) {
    __shared__ unsigned S[FB_WARPS][32][17];
    const int w = threadIdx.x >> 5;
    const int lane = threadIdx.x & 31;
    const int nf = g_nflag;

    for (int f = blockIdx.x * FB_WARPS + w; f < nf; f += FB_BLOCKS * FB_WARPS) {
        const int gq = g_flagq[f];
        const int cloud = gq >> 13;
        const int q = gq & (Mc - 1);
        const float* cb = coords + (size_t)cloud * Mc * 3;
        const float4* cp = (const float4*)cb;
        const float qx = cb[3 * q], qy = cb[3 * q + 1], qz = cb[3 * q + 2];

        unsigned tk[16];
#pragma unroll
        for (int t = 0; t < 16; ++t) tk[t] = 0xFFFFFFFFu;

#pragma unroll 1
        for (int b = 0; b < 32; ++b) {
            const int j0 = lane * 256 + b * 8;
            const float4* p = cp + ((3 * j0) >> 2);
            float4 A = p[0], Bv = p[1], C = p[2], D = p[3], E = p[4], F = p[5];
            float x8[8] = {A.x, A.w, Bv.z, C.y, D.x, D.w, E.z, F.y};
            float y8[8] = {A.y, Bv.x, Bv.w, C.z, D.y, E.x, E.w, F.z};
            float z8[8] = {A.z, Bv.y, C.x, C.w, D.z, E.y, F.x, F.w};
            unsigned bk[8];
#pragma unroll
            for (int i = 0; i < 8; ++i) {
                float dx = x8[i] - qx, dy = y8[i] - qy, dz = z8[i] - qz;
                float d = fmaf(dz, dz, fmaf(dy, dy, dx * dx));
                bk[i] = (__float_as_uint(d) & 0xFFFFE000u) | (unsigned)(j0 + i);
            }
            sort8(bk);
#pragma unroll
            for (int i = 0; i < 8; ++i) tk[15 - i] = min(tk[15 - i], bk[i]);
            clean16(tk);
        }

#pragma unroll
        for (int t = 0; t < 16; ++t) S[w][lane][t] = tk[t];
        __syncwarp();
#pragma unroll
        for (int s = 1; s < 32; s <<= 1) {
            if ((lane & (2 * s - 1)) == 0) {
                unsigned ok[16];
#pragma unroll
                for (int t = 0; t < 16; ++t) ok[t] = S[w][lane + s][t];
#pragma unroll
                for (int t = 0; t < 16; ++t) tk[t] = min(tk[t], ok[15 - t]);
                clean16(tk);
#pragma unroll
                for (int t = 0; t < 16; ++t) S[w][lane][t] = tk[t];
            }
            __syncwarp();
        }
        if (lane == 0) {
            int* out = g_knn + (size_t)gq * KF;
            const int goff = cloud * Mc;
#pragma unroll
            for (int t = 0; t < 16; ++t) out[t] = goff + (int)(tk[t] & 0x1FFFu);

            double acc[6] = {0, 0, 0, 0, 0, 0};
            const float si = scores[gq];
            const float xi = cb[3 * q], yi = cb[3 * q + 1], zi = cb[3 * q + 2];
            float nsum = 0.0f;
#pragma unroll
            for (int r = 0; r < KF; ++r) {
                const int n = goff + (int)(tk[r] & 0x1FFFu);
                const float sn = scores[n];
                const float sd = fabsf(si - sn);
                const float x = (1.0f - sd) * 2.0f;
                const float sig = 1.0f / (1.0f + expf(-x));
                if (r < KN) {
                    const float dx = xi - coords[3 * n];
                    const float dy = yi - coords[3 * n + 1];
                    const float dz = zi - coords[3 * n + 2];
                    const float dist = sqrtf(dx * dx + dy * dy + dz * dz);
                    const float wv = expf(-dist * 10.0f);
                    acc[0] += (double)(wv * sd * sd);
                    acc[1] += (double)wv;
                    acc[2] += (double)logf(sig + 1e-8f);
                    nsum += sn;
                } else {
                    acc[3] += (double)logf(1.0f - sig + 1e-8f);
                }
            }
            const float dm = si - nsum * 0.125f;
            acc[4] = (double)(dm * dm);

            int b = (int)(si * (float)NB);
            b = b < 0 ? 0 : (b > NB - 1 ? NB - 1 : b);
            int hcnt = g_hist[cloud][b];
            hcnt = hcnt > BCAP ? BCAP : hcnt;
            int rk = 0;
            const int* mem = &g_members[cloud][b * BCAP];
            for (int k = 0; k < hcnt; ++k) {
                const int m = mem[k];
                const float sm = scores[(cloud << 13) + m];
                rk += (sm < si) || (sm == si && m < q);
            }
            const int rank = g_pref[cloud][b] + rk;
            const float df = si - (float)rank * (1.0f / (float)(Mc - 1));
            acc[5] = (double)(df * df);
#pragma unroll
            for (int k = 0; k < 6; ++k) atomicAdd(&g_acc[k], acc[k]);
        }
        __syncwarp();
    }
}

// ================= zero =================
__global__ void zero_kernel() {
    const int t = blockIdx.x * blockDim.x + threadIdx.x;
    if (t < 8) g_acc[t] = 0.0;
    if (t == 8) g_nflag = 0;
    const int total = Bc * NB + 2 * Bc * NCELL;
    for (int i = t; i < total; i += gridDim.x * blockDim.x) {
        if (i < Bc * NB) ((int*)g_hist)[i] = 0;
        else if (i < Bc * NB + Bc * NCELL) ((int*)g_chist)[i - Bc * NB] = 0;
        else ((int*)g_cfill)[i - Bc * NB - Bc * NCELL] = 0;
    }
}

// ============ rank bucketing + cell histogram (fused per-point pass) ============
__global__ void rank_cell_build(const float* __restrict__ scores,
                                const float* __restrict__ coords) {
    const int i = blockIdx.x * blockDim.x + threadIdx.x;
    if (i >= Nc) return;
    const int cloud = i >> 13;
    const int local = i & (Mc - 1);
    const float s = scores[i];
    int b = (int)(s * (float)NB);
    b = b < 0 ? 0 : (b > NB - 1 ? NB - 1 : b);
    const int slot = atomicAdd(&g_hist[cloud][b], 1);
    if (slot < BCAP) g_members[cloud][b * BCAP + slot] = local;

    const unsigned code = morton_of(coords[3 * i], coords[3 * i + 1], coords[3 * i + 2]);
    atomicAdd(&g_chist[cloud][code], 1);
}

__global__ void prefix_kernel() {       // scores hist: 4096 per cloud
    __shared__ int sc[1024];
    const int cloud = blockIdx.x;
    const int t = threadIdx.x;
    const int base = t * 4;
    int h0 = g_hist[cloud][base + 0];
    int h1 = g_hist[cloud][base + 1];
    int h2 = g_hist[cloud][base + 2];
    int h3 = g_hist[cloud][base + 3];
    int sum = h0 + h1 + h2 + h3;
    sc[t] = sum;
    __syncthreads();
    for (int off = 1; off < 1024; off <<= 1) {
        int v = (t >= off) ? sc[t - off] : 0;
        __syncthreads();
        sc[t] += v;
        __syncthreads();
    }
    int excl = sc[t] - sum;
    g_pref[cloud][base + 0] = excl; excl += h0;
    g_pref[cloud][base + 1] = excl; excl += h1;
    g_pref[cloud][base + 2] = excl; excl += h2;
    g_pref[cloud][base + 3] = excl;
}

__global__ void cell_prefix_kernel() {  // cell hist: 4096 per cloud (same shape)
    __shared__ int sc[1024];
    const int cloud = blockIdx.x;
    const int t = threadIdx.x;
    const int base = t * 4;
    int h0 = g_chist[cloud][base + 0];
    int h1 = g_chist[cloud][base + 1];
    int h2 = g_chist[cloud][base + 2];
    int h3 = g_chist[cloud][base + 3];
    int sum = h0 + h1 + h2 + h3;
    sc[t] = sum;
    __syncthreads();
    for (int off = 1; off < 1024; off <<= 1) {
        int v = (t >= off) ? sc[t - off] : 0;
        __syncthreads();
        sc[t] += v;
        __syncthreads();
    }
    int excl = sc[t] - sum;
    g_cpref[cloud][base + 0] = excl; excl += h0;
    g_cpref[cloud][base + 1] = excl; excl += h1;
    g_cpref[cloud][base + 2] = excl; excl += h2;
    g_cpref[cloud][base + 3] = excl;
}

__global__ void cell_scatter_kernel(const float* __restrict__ coords) {
    const int i = blockIdx.x * blockDim.x + threadIdx.x;
    if (i >= Nc) return;
    const int cloud = i >> 13;
    const int local = i & (Mc - 1);
    const unsigned code = morton_of(coords[3 * i], coords[3 * i + 1], coords[3 * i + 2]);
    const int pos = g_cpref[cloud][code] + atomicAdd(&g_cfill[cloud][code], 1);
    g_qperm[cloud * Mc + pos] = local;
}

// ================= finalize =================
__global__ void finalize_kernel(float* out) {
    const double l_loc = g_acc[0] / fmax(g_acc[1], 1e-8);
    const double l_pos = -g_acc[2] / (double)((size_t)Nc * KN);
    const double l_neg = -g_acc[3] / (double)((size_t)Nc * KN);
    const double l_con = l_pos + l_neg;
    const double l_smooth = g_acc[4] / (double)Nc;
    const double l_dist = g_acc[5] / (double)Nc;
    out[0] = (float)(1.0 * l_loc + 0.5 * l_con + 0.3 * l_dist + 0.2 * l_smooth);
}

extern "C" void kernel_launch(void* const* d_in, const int* in_sizes, int n_in,
                              void* d_out, int out_size) {
    const float* scores = (const float*)d_in[0];
    const float* coords = (const float*)d_in[1];
    (void)in_sizes; (void)n_in; (void)out_size;

    cudaFuncSetAttribute(knn_kernel,
                         cudaFuncAttributeMaxDynamicSharedMemorySize, SM_KNN_TOTAL);
    const int SEL_SMEM = (QPB * 136 + QPB * 68) * (int)sizeof(unsigned)
                       + QPB * (int)sizeof(int);
    cudaFuncSetAttribute(select_kernel,
                         cudaFuncAttributeMaxDynamicSharedMemorySize, SEL_SMEM);

    zero_kernel<<<32, 1024>>>();
    rank_cell_build<<<Nc / 256, 256>>>(scores, coords);
    prefix_kernel<<<Bc, 1024>>>();
    cell_prefix_kernel<<<Bc, 1024>>>();
    cell_scatter_kernel<<<Nc / 256, 256>>>(coords);
    knn_kernel<<<Bc * QBLKS, KTH, SM_KNN_TOTAL>>>(coords);
    select_kernel<<<Nc / QPB, KTH, SEL_SMEM>>>(scores, coords);
    fallback_kernel<<<FB_BLOCKS, FB_WARPS * 32>>>(coords, scores);
    finalize_kernel<<<1, 1>>>((float*)d_out);
}

// round 16
// speedup vs baseline: 1.9364x; 1.4444x over previous
#include <cuda_runtime.h>
#include <math.h>
#include <float.h>

#define Bc 2
#define Mc 8192
#define Nc (Bc * Mc)
#define KF 16
#define KN 8
#define NB 4096
#define BCAP 64
#define NCELL 4096              // 16^3 morton cells

#define QPB 64                  // queries per block (knn/select)
#define SPLITS 8
#define KTH 512
#define QBLKS 128               // per cloud; knn grid = 256
#define PASS_CANDS 4096         // candidates staged per pass (64KB SoA)
#define SCAP 64                 // survivor cap per (query, slice)
#define CCAP 2048               // compacted-candidate cap per window
#define CPAD (CCAP + 32)

// ---- scratch (device globals; no allocation allowed) ----
__device__ int      g_knn[(size_t)Nc * KF];
__device__ double   g_acc[8];
__device__ int      g_hist[Bc][NB];
__device__ int      g_pref[Bc][NB];
__device__ int      g_members[Bc][NB * BCAP];
__device__ int      g_nflag;
__device__ int      g_flagq[Nc];
__device__ unsigned g_survk[Nc][SPLITS][SCAP];  // (d18)<<13 | idx13
__device__ int      g_cnt[Nc][SPLITS];
__device__ int      g_chist[Bc][NCELL];
__device__ int      g_cpref[Bc][NCELL];
__device__ int      g_cfill[Bc][NCELL];
__device__ int      g_qperm[Bc * Mc];

// ----- u32 compare-exchange: a=min, b=max -----
__device__ __forceinline__ void cx(unsigned& a, unsigned& b) {
    unsigned lo = min(a, b);
    b = max(a, b);
    a = lo;
}

__device__ __forceinline__ void sort8(unsigned k[8]) {
    cx(k[0],k[1]); cx(k[2],k[3]); cx(k[4],k[5]); cx(k[6],k[7]);
    cx(k[0],k[2]); cx(k[1],k[3]); cx(k[4],k[6]); cx(k[5],k[7]);
    cx(k[1],k[2]); cx(k[5],k[6]);
    cx(k[0],k[4]); cx(k[1],k[5]); cx(k[2],k[6]); cx(k[3],k[7]);
    cx(k[2],k[4]); cx(k[3],k[5]);
    cx(k[1],k[2]); cx(k[3],k[4]); cx(k[5],k[6]);
}

__device__ __forceinline__ void clean8(unsigned k[8]) {
    cx(k[0],k[4]); cx(k[1],k[5]); cx(k[2],k[6]); cx(k[3],k[7]);
    cx(k[0],k[2]); cx(k[1],k[3]); cx(k[4],k[6]); cx(k[5],k[7]);
    cx(k[0],k[1]); cx(k[2],k[3]); cx(k[4],k[5]); cx(k[6],k[7]);
}

__device__ __forceinline__ void clean16(unsigned k[16]) {
#pragma unroll
    for (int j = 8; j; j >>= 1)
#pragma unroll
        for (int i = 0; i < 16; ++i) {
            int l = i ^ j;
            if (l > i) cx(k[i], k[l]);
        }
}

#define MRGU(SRC_A, SRC_B, LEN, DSTSTMT)                                      \
    {                                                                         \
        int ii = 0, jj = 0;                                                   \
        _Pragma("unroll 1")                                                   \
        for (int r = 0; r < 16; ++r) {                                        \
            unsigned a = (SRC_A)[min(ii, (LEN) - 1)];                         \
            unsigned b = (SRC_B)[min(jj, (LEN) - 1)];                         \
            bool takeA = (jj >= (LEN)) || ((ii < (LEN)) && (a <= b));         \
            unsigned o = takeA ? a : b;                                       \
            ii += takeA; jj += !takeA;                                        \
            DSTSTMT;                                                          \
        }                                                                     \
    }

// 4 distances from SoA via float4 loads: d = ax*x + ay*y + az*z + (w + qw)
__device__ __forceinline__ void dist4s(const float* __restrict__ xs,
                                       const float* __restrict__ ys,
                                       const float* __restrict__ zs,
                                       const float* __restrict__ ws, int j0,
                                       float ax, float ay, float az, float qw,
                                       float d[4]) {
    float4 X = *(const float4*)(xs + j0);
    float4 Y = *(const float4*)(ys + j0);
    float4 Z = *(const float4*)(zs + j0);
    float4 W = *(const float4*)(ws + j0);
    d[0] = fmaf(ax, X.x, fmaf(ay, Y.x, fmaf(az, Z.x, W.x + qw)));
    d[1] = fmaf(ax, X.y, fmaf(ay, Y.y, fmaf(az, Z.y, W.y + qw)));
    d[2] = fmaf(ax, X.z, fmaf(ay, Y.z, fmaf(az, Z.z, W.z + qw)));
    d[3] = fmaf(ax, X.w, fmaf(ay, Y.w, fmaf(az, Z.w, W.w + qw)));
}

// Morton bit expansion
__device__ __forceinline__ unsigned expand3(unsigned v) {
    v &= 0x3FFu;
    v = (v | (v << 16)) & 0x030000FFu;
    v = (v | (v << 8))  & 0x0300F00Fu;
    v = (v | (v << 4))  & 0x030C30C3u;
    v = (v | (v << 2))  & 0x09249249u;
    return v;
}
__device__ __forceinline__ unsigned morton_of(float x, float y, float z) {
    int mx = min(15, max(0, (int)(x + 8.0f)));
    int my = min(15, max(0, (int)(y + 8.0f)));
    int mz = min(15, max(0, (int)(z + 8.0f)));
    return expand3((unsigned)mx) | (expand3((unsigned)my) << 1)
         | (expand3((unsigned)mz) << 2);
}

// ---- knn smem layout (byte offsets) ----
#define SM_STAGE   0                         // 4 arrays x 4096 x 4 = 65536
#define SM_COMPACT 65536                     // 5 arrays x CPAD x 4 = 41600
#define SM_TAU     (SM_COMPACT + CPAD * 5 * 4)
#define SM_SX      (SM_TAU + 256)
#define SM_SY      (SM_SX + 256)
#define SM_SZ      (SM_SY + 256)
#define SM_ST      (SM_SZ + 256)
#define SM_STATF   (SM_ST + 256)             // 4 floats
#define SM_KC      (SM_STATF + 16)           // 1 int
#define SM_WSUM    (SM_KC + 16)              // 16 ints
#define SM_KNN_TOTAL (SM_WSUM + 64)

// ================= Kernel A: tau + block-pruned filter =================
extern "C" __global__ void __launch_bounds__(KTH, 2)
knn_kernel(const float* __restrict__ coords) {
    extern __shared__ unsigned char sraw[];
    float* xs = (float*)(sraw + SM_STAGE);
    float* ys = xs + PASS_CANDS;
    float* zs = ys + PASS_CANDS;
    float* ws = zs + PASS_CANDS;
    float* ccx = (float*)(sraw + SM_COMPACT);
    float* ccy = ccx + CPAD;
    float* ccz = ccy + CPAD;
    float* ccw = ccz + CPAD;
    int*   cidx = (int*)(ccw + CPAD);
    unsigned* bufA = (unsigned*)(sraw + SM_COMPACT);   // overlay (pre-Phase-B)
    unsigned* bufB = bufA + QPB * 68;
    unsigned* tau_sm = (unsigned*)(sraw + SM_TAU);
    float* sx = (float*)(sraw + SM_SX);
    float* sy = (float*)(sraw + SM_SY);
    float* sz = (float*)(sraw + SM_SZ);
    float* st = (float*)(sraw + SM_ST);
    float* statf = (float*)(sraw + SM_STATF);
    int*   kcS = (int*)(sraw + SM_KC);
    int*   wsS = (int*)(sraw + SM_WSUM);

    const int tid = threadIdx.x;
    const int cloud = blockIdx.x >> 7;
    const int qblk = blockIdx.x & 127;
    const int qLocal = tid & (QPB - 1);
    const int split = tid >> 6;            // warp-uniform

    const float* cb = coords + (size_t)cloud * Mc * 3;
    const float4* cp = (const float4*)cb;
    const int q = g_qperm[cloud * Mc + qblk * QPB + qLocal];
    const int gq = cloud * Mc + q;

    const float qx = cb[3 * q], qy = cb[3 * q + 1], qz = cb[3 * q + 2];
    const float qw = fmaf(qx, qx, fmaf(qy, qy, qz * qz));
    const float ax = -2.0f * qx, ay = -2.0f * qy, az = -2.0f * qz;
    const int sbase = split << 9;

    // ---- Phase A: keep-8 over 1024-point sample (128/thread), uniform LDG ----
    unsigned tk[8];
#pragma unroll
    for (int t = 0; t < 8; ++t) tk[t] = 0xFFFFFFFFu;

#pragma unroll 1
    for (int b = 0; b < 16; ++b) {
        const int j0 = (b < 8) ? (sbase + b * 8)
                               : (PASS_CANDS + sbase + (b - 8) * 8);
        const float4* p = cp + ((3 * j0) >> 2);   // j0 % 8 == 0 -> aligned
        float4 A = p[0], Bv = p[1], C = p[2], D = p[3], E = p[4], F = p[5];
        float x8[8] = {A.x, A.w, Bv.z, C.y, D.x, D.w, E.z, F.y};
        float y8[8] = {A.y, Bv.x, Bv.w, C.z, D.y, E.x, E.w, F.z};
        float z8[8] = {A.z, Bv.y, C.x, C.w, D.z, E.y, F.x, F.w};
        unsigned bk[8];
#pragma unroll
        for (int i = 0; i < 8; ++i) {
            float w = fmaf(x8[i], x8[i], fmaf(y8[i], y8[i], z8[i] * z8[i]));
            float d = fmaf(ax, x8[i], fmaf(ay, y8[i], fmaf(az, z8[i], w + qw)));
            bk[i] = __float_as_uint(d) & 0x7FFFF800u;
        }
        sort8(bk);
#pragma unroll
        for (int i = 0; i < 8; ++i) tk[i] = min(tk[i], bk[7 - i]);
        clean8(tk);
    }

    // ---- merge 8 sorted-8 keys -> 16th smallest -> tau ----
    const int rowA = qLocal * 68 + split * 8;
#pragma unroll
    for (int t = 0; t < 8; ++t) bufA[rowA + t] = tk[t];
    __syncthreads();

    if (split < 4) {
        const unsigned* sa = bufA + qLocal * 68 + split * 16;
        unsigned* dst = bufB + qLocal * 68 + split * 16;
        MRGU(sa, sa + 8, 8, dst[r] = o);
    }
    __syncthreads();
    if (split < 2) {
        const unsigned* sa = bufB + qLocal * 68 + split * 32;
        unsigned* dst = bufA + qLocal * 68 + split * 16;
        MRGU(sa, sa + 16, 16, dst[r] = o);
    }
    __syncthreads();
    if (split == 0) {
        const unsigned* sa = bufA + qLocal * 68;
        unsigned last = 0;
        MRGU(sa, sa + 16, 16, last = o);
        tau_sm[qLocal] = last | 0x7FFu;    // bin-top: upper bound of sample d16
    }
    __syncthreads();
    const float tauf = __uint_as_float(tau_sm[qLocal]);

    // ---- block stats: center + prune radius ----
    if (split == 0) {
        sx[qLocal] = qx; sy[qLocal] = qy; sz[qLocal] = qz;
        st[qLocal] = sqrtf(fmaxf(tauf, 0.0f));
    }
    __syncthreads();
    if (tid < 32) {
        float mnx = fminf(sx[tid], sx[tid + 32]), mxx = fmaxf(sx[tid], sx[tid + 32]);
        float mny = fminf(sy[tid], sy[tid + 32]), mxy = fmaxf(sy[tid], sy[tid + 32]);
        float mnz = fminf(sz[tid], sz[tid + 32]), mxz = fmaxf(sz[tid], sz[tid + 32]);
        float mst = fmaxf(st[tid], st[tid + 32]);
#pragma unroll
        for (int o = 16; o; o >>= 1) {
            mnx = fminf(mnx, __shfl_xor_sync(0xffffffffu, mnx, o));
            mxx = fmaxf(mxx, __shfl_xor_sync(0xffffffffu, mxx, o));
            mny = fminf(mny, __shfl_xor_sync(0xffffffffu, mny, o));
            mxy = fmaxf(mxy, __shfl_xor_sync(0xffffffffu, mxy, o));
            mnz = fminf(mnz, __shfl_xor_sync(0xffffffffu, mnz, o));
            mxz = fmaxf(mxz, __shfl_xor_sync(0xffffffffu, mxz, o));
            mst = fmaxf(mst, __shfl_xor_sync(0xffffffffu, mst, o));
        }
        const float cx0 = 0.5f * (mnx + mxx);
        const float cy0 = 0.5f * (mny + mxy);
        const float cz0 = 0.5f * (mnz + mxz);
        float dx1 = sx[tid] - cx0, dy1 = sy[tid] - cy0, dz1 = sz[tid] - cz0;
        float r1 = sqrtf(fmaf(dz1, dz1, fmaf(dy1, dy1, dx1 * dx1)));
        float dx2 = sx[tid + 32] - cx0, dy2 = sy[tid + 32] - cy0, dz2 = sz[tid + 32] - cz0;
        float r2 = sqrtf(fmaf(dz2, dz2, fmaf(dy2, dy2, dx2 * dx2)));
        float rb = fmaxf(r1, r2);
#pragma unroll
        for (int o = 16; o; o >>= 1)
            rb = fmaxf(rb, __shfl_xor_sync(0xffffffffu, rb, o));
        if (tid == 0) {
            float pr = rb + mst + 0.01f;
            statf[0] = cx0; statf[1] = cy0; statf[2] = cz0; statf[3] = pr * pr;
        }
    }
    __syncthreads();
    const float cx0 = statf[0], cy0 = statf[1], cz0 = statf[2];
    const float pruneR2 = statf[3];

    // ---- Phase B: stage + block-prune + per-query filter ----
    int cnt = 0;
    unsigned* seg = &g_survk[gq][split][0];
    const int lane = tid & 31, wid = tid >> 5;

#pragma unroll 1
    for (int pass = 0; pass < 2; ++pass) {
        __syncthreads();
        const int wbase = pass * PASS_CANDS;
        int kcnt = 0;
        unsigned kmask = 0;
#pragma unroll
        for (int k = 0; k < 8; ++k) {
            const int i = tid + k * KTH;
            const int jg = wbase + i;
            float x = cb[3 * jg], y = cb[3 * jg + 1], z = cb[3 * jg + 2];
            float w = fmaf(x, x, fmaf(y, y, z * z));
            xs[i] = x; ys[i] = y; zs[i] = z; ws[i] = w;
            float dx = x - cx0, dy = y - cy0, dz = z - cz0;
            float dc2 = fmaf(dz, dz, fmaf(dy, dy, dx * dx));
            bool keep = (dc2 <= pruneR2);
            kmask |= ((unsigned)keep) << k;
            kcnt += (int)keep;
        }
        int incl = kcnt;
#pragma unroll
        for (int o = 1; o < 32; o <<= 1) {
            int n = __shfl_up_sync(0xffffffffu, incl, o);
            if (lane >= o) incl += n;
        }
        if (lane == 31) wsS[wid] = incl;
        __syncthreads();
        if (wid == 0) {
            int s = (lane < 16) ? wsS[lane] : 0;
#pragma unroll
            for (int o = 1; o < 16; o <<= 1) {
                int n = __shfl_up_sync(0xffffffffu, s, o);
                if (lane >= o) s += n;
            }
            if (lane < 16) wsS[lane] = s;
            if (lane == 15) kcS[0] = s;
        }
        __syncthreads();
        const int Kc = kcS[0];

        if (Kc <= CCAP) {
            int off = (wid ? wsS[wid - 1] : 0) + incl - kcnt;
#pragma unroll
            for (int k = 0; k < 8; ++k) {
                if ((kmask >> k) & 1u) {
                    const int i = tid + k * KTH;
                    ccx[off] = xs[i]; ccy[off] = ys[i];
                    ccz[off] = zs[i]; ccw[off] = ws[i];
                    cidx[off] = wbase + i;
                    ++off;
                }
            }
            if (tid == 0) {
                const int Kcp = (Kc + 31) & ~31;
                for (int j = Kc; j < Kcp; ++j) {
                    ccx[j] = 0.0f; ccy[j] = 0.0f; ccz[j] = 0.0f;
                    ccw[j] = 3.0e38f; cidx[j] = 0;
                }
            }
            __syncthreads();
            const int slice = ((Kc + 31) & ~31) >> 3;
            const int j0b = split * slice;
#pragma unroll 1
            for (int j0 = j0b; j0 < j0b + slice; j0 += 4) {
                float dv[4];
                dist4s(ccx, ccy, ccz, ccw, j0, ax, ay, az, qw, dv);
#pragma unroll
                for (int i = 0; i < 4; ++i) {
                    if (dv[i] <= tauf) {
                        if (cnt < SCAP)
                            seg[cnt] = (__float_as_uint(dv[i]) & 0x7FFFE000u)
                                     | (unsigned)cidx[j0 + i];
                        ++cnt;
                    }
                }
            }
        } else {
            const int gbase = wbase + sbase;
#pragma unroll 2
            for (int j0 = 0; j0 < 512; j0 += 4) {
                float dv[4];
                dist4s(xs, ys, zs, ws, sbase + j0, ax, ay, az, qw, dv);
#pragma unroll
                for (int i = 0; i < 4; ++i) {
                    if (dv[i] <= tauf) {
                        if (cnt < SCAP)
                            seg[cnt] = (__float_as_uint(dv[i]) & 0x7FFFE000u)
                                     | (unsigned)(gbase + j0 + i);
                        ++cnt;
                    }
                }
            }
        }
    }
    g_cnt[gq][split] = cnt;
}

// ====== select: top-16 of survivors (8 threads/query) + fused losses ======
extern "C" __global__ void __launch_bounds__(KTH, 2)
select_kernel(const float* __restrict__ scores, const float* __restrict__ coords) {
    extern __shared__ unsigned char sraw[];
    unsigned* bufA = (unsigned*)sraw;              // [QPB][136]
    unsigned* bufB = bufA + QPB * 136;             // [QPB][68]
    int* ovf = (int*)(bufB + QPB * 68);            // [QPB]
    __shared__ double red[16][6];

    const int tid = threadIdx.x;
    const int qLocal = tid & (QPB - 1);
    const int split = tid >> 6;
    const int gq = blockIdx.x * QPB + qLocal;
    const int goff = (gq >> 13) << 13;

    if (split == 0) ovf[qLocal] = 0;
    __syncthreads();

    int cn = g_cnt[gq][split];
    if (cn > SCAP) { ovf[qLocal] = 1; cn = SCAP; }
    const unsigned* seg = &g_survk[gq][split][0];

    unsigned tk[16];
#pragma unroll
    for (int t = 0; t < 16; ++t) tk[t] = 0xFFFFFFFFu;

#pragma unroll 1
    for (int k = 0; k < cn; k += 8) {
        unsigned bk[8];
#pragma unroll
        for (int i = 0; i < 8; ++i)
            bk[i] = (k + i < cn) ? seg[k + i] : 0xFFFFFFFFu;
        sort8(bk);
#pragma unroll
        for (int i = 0; i < 8; ++i) tk[15 - i] = min(tk[15 - i], bk[i]);
        clean16(tk);
    }

    const int rowA = qLocal * 136 + split * 16;
#pragma unroll
    for (int t = 0; t < 16; ++t) bufA[rowA + t] = tk[t];
    __syncthreads();

    if (split < 4) {
        const unsigned* sa = bufA + qLocal * 136 + split * 32;
        unsigned* dst = bufB + qLocal * 68 + split * 16;
        MRGU(sa, sa + 16, 16, dst[r] = o);
    }
    __syncthreads();
    if (split < 2) {
        const unsigned* sa = bufB + qLocal * 68 + split * 32;
        unsigned* dst = bufA + qLocal * 136 + split * 16;
        MRGU(sa, sa + 16, 16, dst[r] = o);
    }
    __syncthreads();

    float fac[6] = {0, 0, 0, 0, 0, 0};
    if (split == 0) {
        int* out = g_knn + (size_t)gq * KF;
        const unsigned* sa = bufA + qLocal * 136;
        unsigned* nbrow = bufB + qLocal * 68;
        MRGU(sa, sa + 16, 16, {
            unsigned gi = o & 0x1FFFu;
            out[r] = goff + (int)gi;
            nbrow[r] = gi;
        });
        if (ovf[qLocal]) {
            int slot = atomicAdd(&g_nflag, 1);
            g_flagq[slot] = gq;
        } else {
            const float si = scores[gq];
            const float xi = coords[3 * gq], yi = coords[3 * gq + 1], zi = coords[3 * gq + 2];
            float nsum = 0.0f;
#pragma unroll
            for (int r = 0; r < KF; ++r) {
                const int n = goff + (int)nbrow[r];
                const float sn = scores[n];
                const float sd = fabsf(si - sn);
                const float x = (1.0f - sd) * 2.0f;
                const float sig = 1.0f / (1.0f + expf(-x));
                if (r < KN) {
                    const float dx = xi - coords[3 * n];
                    const float dy = yi - coords[3 * n + 1];
                    const float dz = zi - coords[3 * n + 2];
                    const float dist = sqrtf(dx * dx + dy * dy + dz * dz);
                    const float w = expf(-dist * 10.0f);
                    fac[0] += w * sd * sd;
                    fac[1] += w;
                    fac[2] += logf(sig + 1e-8f);
                    nsum += sn;
                } else {
                    fac[3] += logf(1.0f - sig + 1e-8f);
                }
            }
            const float dm = si - nsum * 0.125f;
            fac[4] = dm * dm;

            const int cloud = gq >> 13;
            const int local = gq & (Mc - 1);
            int b = (int)(si * (float)NB);
            b = b < 0 ? 0 : (b > NB - 1 ? NB - 1 : b);
            int hcnt = g_hist[cloud][b];
            hcnt = hcnt > BCAP ? BCAP : hcnt;
            int rk = 0;
            const int* mem = &g_members[cloud][b * BCAP];
            for (int k = 0; k < hcnt; ++k) {
                const int m = mem[k];
                const float sm = scores[(cloud << 13) + m];
                rk += (sm < si) || (sm == si && m < local);
            }
            const int rank = g_pref[cloud][b] + rk;
            const float df = si - (float)rank * (1.0f / (float)(Mc - 1));
            fac[5] = df * df;
        }
    }

    const int lane = threadIdx.x & 31;
    const int wid = threadIdx.x >> 5;
#pragma unroll
    for (int k = 0; k < 6; ++k)
#pragma unroll
        for (int o = 16; o; o >>= 1)
            fac[k] += __shfl_down_sync(0xffffffffu, fac[k], o);
    if (lane == 0)
#pragma unroll
        for (int k = 0; k < 6; ++k) red[wid][k] = (double)fac[k];
    __syncthreads();
    if (wid == 0 && lane < 6) {
        double s = 0.0;
#pragma unroll
        for (int w = 0; w < 16; ++w) s += red[w][lane];
        atomicAdd(&g_acc[lane], s);
    }
}

// ============ exact fallback for overflowed queries (rare) + loss ============
#define FB_BLOCKS 296
#define FB_WARPS 8
__global__ void __launch_bounds__(FB_WARPS * 32)
fallback_kernel(const float* __restrict__ coords, const float* __restrict__ scores) {
    __shared__ unsigned S[FB_WARPS][32][17];
    const int w = threadIdx.x >> 5;
    const int lane = threadIdx.x & 31;
    const int nf = g_nflag;

    for (int f = blockIdx.x * FB_WARPS + w; f < nf; f += FB_BLOCKS * FB_WARPS) {
        const int gq = g_flagq[f];
        const int cloud = gq >> 13;
        const int q = gq & (Mc - 1);
        const float* cb = coords + (size_t)cloud * Mc * 3;
        const float4* cp = (const float4*)cb;
        const float qx = cb[3 * q], qy = cb[3 * q + 1], qz = cb[3 * q + 2];

        unsigned tk[16];
#pragma unroll
        for (int t = 0; t < 16; ++t) tk[t] = 0xFFFFFFFFu;

#pragma unroll 1
        for (int b = 0; b < 32; ++b) {
            const int j0 = lane * 256 + b * 8;
            const float4* p = cp + ((3 * j0) >> 2);
            float4 A = p[0], Bv = p[1], C = p[2], D = p[3], E = p[4], F = p[5];
            float x8[8] = {A.x, A.w, Bv.z, C.y, D.x, D.w, E.z, F.y};
            float y8[8] = {A.y, Bv.x, Bv.w, C.z, D.y, E.x, E.w, F.z};
            float z8[8] = {A.z, Bv.y, C.x, C.w, D.z, E.y, F.x, F.w};
            unsigned bk[8];
#pragma unroll
            for (int i = 0; i < 8; ++i) {
                float dx = x8[i] - qx, dy = y8[i] - qy, dz = z8[i] - qz;
                float d = fmaf(dz, dz, fmaf(dy, dy, dx * dx));
                bk[i] = (__float_as_uint(d) & 0xFFFFE000u) | (unsigned)(j0 + i);
            }
            sort8(bk);
#pragma unroll
            for (int i = 0; i < 8; ++i) tk[15 - i] = min(tk[15 - i], bk[i]);
            clean16(tk);
        }

#pragma unroll
        for (int t = 0; t < 16; ++t) S[w][lane][t] = tk[t];
        __syncwarp();
#pragma unroll
        for (int s = 1; s < 32; s <<= 1) {
            if ((lane & (2 * s - 1)) == 0) {
                unsigned ok[16];
#pragma unroll
                for (int t = 0; t < 16; ++t) ok[t] = S[w][lane + s][t];
#pragma unroll
                for (int t = 0; t < 16; ++t) tk[t] = min(tk[t], ok[15 - t]);
                clean16(tk);
#pragma unroll
                for (int t = 0; t < 16; ++t) S[w][lane][t] = tk[t];
            }
            __syncwarp();
        }
        if (lane == 0) {
            int* out = g_knn + (size_t)gq * KF;
            const int goff = cloud * Mc;
#pragma unroll
            for (int t = 0; t < 16; ++t) out[t] = goff + (int)(tk[t] & 0x1FFFu);

            double acc[6] = {0, 0, 0, 0, 0, 0};
            const float si = scores[gq];
            const float xi = cb[3 * q], yi = cb[3 * q + 1], zi = cb[3 * q + 2];
            float nsum = 0.0f;
#pragma unroll
            for (int r = 0; r < KF; ++r) {
                const int n = goff + (int)(tk[r] & 0x1FFFu);
                const float sn = scores[n];
                const float sd = fabsf(si - sn);
                const float x = (1.0f - sd) * 2.0f;
                const float sig = 1.0f / (1.0f + expf(-x));
                if (r < KN) {
                    const float dx = xi - coords[3 * n];
                    const float dy = yi - coords[3 * n + 1];
                    const float dz = zi - coords[3 * n + 2];
                    const float dist = sqrtf(dx * dx + dy * dy + dz * dz);
                    const float wv = expf(-dist * 10.0f);
                    acc[0] += (double)(wv * sd * sd);
                    acc[1] += (double)wv;
                    acc[2] += (double)logf(sig + 1e-8f);
                    nsum += sn;
                } else {
                    acc[3] += (double)logf(1.0f - sig + 1e-8f);
                }
            }
            const float dm = si - nsum * 0.125f;
            acc[4] = (double)(dm * dm);

            int b = (int)(si * (float)NB);
            b = b < 0 ? 0 : (b > NB - 1 ? NB - 1 : b);
            int hcnt = g_hist[cloud][b];
            hcnt = hcnt > BCAP ? BCAP : hcnt;
            int rk = 0;
            const int* mem = &g_members[cloud][b * BCAP];
            for (int k = 0; k < hcnt; ++k) {
                const int m = mem[k];
                const float sm = scores[(cloud << 13) + m];
                rk += (sm < si) || (sm == si && m < q);
            }
            const int rank = g_pref[cloud][b] + rk;
            const float df = si - (float)rank * (1.0f / (float)(Mc - 1));
            acc[5] = (double)(df * df);
#pragma unroll
            for (int k = 0; k < 6; ++k) atomicAdd(&g_acc[k], acc[k]);
        }
        __syncwarp();
    }
}

// ================= zero =================
__global__ void zero_kernel() {
    const int t = blockIdx.x * blockDim.x + threadIdx.x;
    if (t < 8) g_acc[t] = 0.0;
    if (t == 8) g_nflag = 0;
    const int total = Bc * NB + 2 * Bc * NCELL;
    for (int i = t; i < total; i += gridDim.x * blockDim.x) {
        if (i < Bc * NB) ((int*)g_hist)[i] = 0;
        else if (i < Bc * NB + Bc * NCELL) ((int*)g_chist)[i - Bc * NB] = 0;
        else ((int*)g_cfill)[i - Bc * NB - Bc * NCELL] = 0;
    }
}

// ============ rank bucketing + cell histogram (fused per-point pass) ============
__global__ void rank_cell_build(const float* __restrict__ scores,
                                const float* __restrict__ coords) {
    const int i = blockIdx.x * blockDim.x + threadIdx.x;
    if (i >= Nc) return;
    const int cloud = i >> 13;
    const int local = i & (Mc - 1);
    const float s = scores[i];
    int b = (int)(s * (float)NB);
    b = b < 0 ? 0 : (b > NB - 1 ? NB - 1 : b);
    const int slot = atomicAdd(&g_hist[cloud][b], 1);
    if (slot < BCAP) g_members[cloud][b * BCAP + slot] = local;

    const unsigned code = morton_of(coords[3 * i], coords[3 * i + 1], coords[3 * i + 2]);
    atomicAdd(&g_chist[cloud][code], 1);
}

// fused prefix for both 4096-bin histograms: grid = 4 (2 arrays x 2 clouds)
__global__ void prefix_both_kernel() {
    __shared__ int sc[1024];
    const int which = blockIdx.x >> 1;   // 0: score hist, 1: cell hist
    const int cloud = blockIdx.x & 1;
    const int* hist = which ? &g_chist[cloud][0] : &g_hist[cloud][0];
    int* pref = which ? &g_cpref[cloud][0] : &g_pref[cloud][0];
    const int t = threadIdx.x;
    const int base = t * 4;
    int h0 = hist[base + 0];
    int h1 = hist[base + 1];
    int h2 = hist[base + 2];
    int h3 = hist[base + 3];
    int sum = h0 + h1 + h2 + h3;
    sc[t] = sum;
    __syncthreads();
    for (int off = 1; off < 1024; off <<= 1) {
        int v = (t >= off) ? sc[t - off] : 0;
        __syncthreads();
        sc[t] += v;
        __syncthreads();
    }
    int excl = sc[t] - sum;
    pref[base + 0] = excl; excl += h0;
    pref[base + 1] = excl; excl += h1;
    pref[base + 2] = excl; excl += h2;
    pref[base + 3] = excl;
}

__global__ void cell_scatter_kernel(const float* __restrict__ coords) {
    const int i = blockIdx.x * blockDim.x + threadIdx.x;
    if (i >= Nc) return;
    const int cloud = i >> 13;
    const int local = i & (Mc - 1);
    const unsigned code = morton_of(coords[3 * i], coords[3 * i + 1], coords[3 * i + 2]);
    const int pos = g_cpref[cloud][code] + atomicAdd(&g_cfill[cloud][code], 1);
    g_qperm[cloud * Mc + pos] = local;
}

// ================= finalize =================
__global__ void finalize_kernel(float* out) {
    const double l_loc = g_acc[0] / fmax(g_acc[1], 1e-8);
    const double l_pos = -g_acc[2] / (double)((size_t)Nc * KN);
    const double l_neg = -g_acc[3] / (double)((size_t)Nc * KN);
    const double l_con = l_pos + l_neg;
    const double l_smooth = g_acc[4] / (double)Nc;
    const double l_dist = g_acc[5] / (double)Nc;
    out[0] = (float)(1.0 * l_loc + 0.5 * l_con + 0.3 * l_dist + 0.2 * l_smooth);
}

extern "C" void kernel_launch(void* const* d_in, const int* in_sizes, int n_in,
                              void* d_out, int out_size) {
    const float* scores = (const float*)d_in[0];
    const float* coords = (const float*)d_in[1];
    (void)in_sizes; (void)n_in; (void)out_size;

    cudaFuncSetAttribute(knn_kernel,
                         cudaFuncAttributeMaxDynamicSharedMemorySize, SM_KNN_TOTAL);
    const int SEL_SMEM = (QPB * 136 + QPB * 68) * (int)sizeof(unsigned)
                       + QPB * (int)sizeof(int);
    cudaFuncSetAttribute(select_kernel,
                         cudaFuncAttributeMaxDynamicSharedMemorySize, SEL_SMEM);

    zero_kernel<<<32, 1024>>>();
    rank_cell_build<<<Nc / 256, 256>>>(scores, coords);
    prefix_both_kernel<<<4, 1024>>>();
    cell_scatter_kernel<<<Nc / 256, 256>>>(coords);
    knn_kernel<<<Bc * QBLKS, KTH, SM_KNN_TOTAL>>>(coords);
    select_kernel<<<Nc / QPB, KTH, SEL_SMEM>>>(scores, coords);
    fallback_kernel<<<FB_BLOCKS, FB_WARPS * 32>>>(coords, scores);
    finalize_kernel<<<1, 1>>>((float*)d_out);
}